// round 6
// baseline (speedup 1.0000x reference)
#include <cuda_runtime.h>
#include <cstdint>

// ---------------------------------------------------------------------------
// PatchCoreAnomalyHead via mma.sync tf32 + cp.async.bulk row-pipelines.
// features[8,4096,1024] -> MLP(1024->512 relu ->256) -> min_m ||p - bank[m]||.
// ---------------------------------------------------------------------------

#define R_TOTAL 32768
#define C_IN    1024
#define C_HID   512
#define C_D     256
#define M_BANK  16384

__device__ float g_H[(size_t)R_TOTAL * C_HID];
__device__ float g_P[(size_t)R_TOTAL * C_D];
__device__ float g_W1T[(size_t)C_HID * C_IN];
__device__ float g_W2T[(size_t)C_D * C_HID];
__device__ float g_m2[M_BANK];
__device__ float g_x2[R_TOTAL];
__device__ float g_pmin[4 * R_TOTAL];

// ---------------------------- helpers --------------------------------------
__device__ __forceinline__ uint32_t smem_u32(const void* p) {
    uint32_t a;
    asm("{ .reg .u64 t; cvta.to.shared.u64 t, %1; cvt.u32.u64 %0, t; }"
        : "=r"(a) : "l"(p));
    return a;
}
// one-row async bulk copy gmem->smem, completion via mbarrier complete_tx
__device__ __forceinline__ void bulk_cp(uint32_t dst, const void* src,
                                        uint32_t bytes, uint32_t mbar) {
    asm volatile(
        "cp.async.bulk.shared::cta.global.mbarrier::complete_tx::bytes "
        "[%0], [%1], %2, [%3];"
        :: "r"(dst), "l"(src), "r"(bytes), "r"(mbar) : "memory");
}
__device__ __forceinline__ void mbar_arrive_tx(uint32_t mbar, uint32_t bytes) {
    asm volatile("mbarrier.arrive.expect_tx.shared.b64 _, [%0], %1;"
                 :: "r"(mbar), "r"(bytes) : "memory");
}
#define MBAR_INIT(a, c) \
    asm volatile("mbarrier.init.shared.b64 [%0], %1;" :: "r"(a), "r"((uint32_t)(c)) : "memory")
#define MBAR_WAIT(a, par) do {                                                  \
    uint32_t _mb = (a), _p = (par), _d;                                         \
    asm volatile("{ .reg .pred p; mbarrier.try_wait.parity.acquire.cta.shared::cta.b64 p, [%1], %2; selp.b32 %0,1,0,p; }" \
                 : "=r"(_d) : "r"(_mb), "r"(_p) : "memory");                    \
    if (!_d) {                                                                  \
        asm volatile("{ .reg .pred P1; WL%=: mbarrier.try_wait.parity.acquire.cta.shared::cta.b64 P1, [%0], %1, 0x989680; @P1 bra.uni WD%=; bra.uni WL%=; WD%=: }" \
                     :: "r"(_mb), "r"(_p) : "memory");                          \
    }                                                                           \
} while (0)

__device__ __forceinline__ void mma_tf32(float (&d)[4],
                                         const uint32_t (&a)[4],
                                         const uint32_t (&b)[2]) {
    asm volatile(
        "mma.sync.aligned.m16n8k8.row.col.f32.tf32.tf32.f32 "
        "{%0,%1,%2,%3}, {%4,%5,%6,%7}, {%8,%9}, {%0,%1,%2,%3};"
        : "+f"(d[0]), "+f"(d[1]), "+f"(d[2]), "+f"(d[3])
        : "r"(a[0]), "r"(a[1]), "r"(a[2]), "r"(a[3]), "r"(b[0]), "r"(b[1]));
}

// k=32 slab, warp tile 64x64 (4 m x 8 n of m16n8k8).
// ALD,BLD ≡ 4 (mod 32) -> all fragment gathers bank-conflict-free.
template <int ALD, int BLD>
__device__ __forceinline__ void compute_k32(const float* __restrict__ aw,
                                            const float* __restrict__ bw,
                                            float (&acc)[4][8][4]) {
#pragma unroll
    for (int s = 0; s < 4; s++) {
        const int k0 = s * 8;
        uint32_t a[4][4], b[8][2];
#pragma unroll
        for (int mi = 0; mi < 4; mi++) {
            const uint32_t* p = (const uint32_t*)(aw + mi * 16 * ALD + k0);
            a[mi][0] = p[0];
            a[mi][1] = p[8 * ALD];
            a[mi][2] = p[4];
            a[mi][3] = p[8 * ALD + 4];
        }
#pragma unroll
        for (int ni = 0; ni < 8; ni++) {
            const uint32_t* p = (const uint32_t*)(bw + ni * 8 * BLD + k0);
            b[ni][0] = p[0];
            b[ni][1] = p[4];
        }
#pragma unroll
        for (int mi = 0; mi < 4; mi++)
#pragma unroll
            for (int ni = 0; ni < 8; ni++)
                mma_tf32(acc[mi][ni], a[mi], b[ni]);
    }
}

// ------------------------- small prep kernels ------------------------------
__global__ void rowsq_kernel(const float* __restrict__ src, float* __restrict__ dst) {
    int i = blockIdx.x * blockDim.x + threadIdx.x;
    const float4* p = (const float4*)(src + (size_t)i * C_D);
    float s = 0.f;
#pragma unroll 8
    for (int q = 0; q < C_D / 4; q++) {
        float4 v = p[q];
        s += v.x * v.x + v.y * v.y + v.z * v.z + v.w * v.w;
    }
    dst[i] = s;
}
__global__ void transpose32(const float* __restrict__ src, float* __restrict__ dst,
                            int R, int C) {
    __shared__ float tile[32][33];
    int bx = blockIdx.x * 32, by = blockIdx.y * 32;
    int tx = threadIdx.x & 31, ty = threadIdx.x >> 5;
#pragma unroll
    for (int i = 0; i < 32; i += 8)
        tile[ty + i][tx] = src[(size_t)(by + ty + i) * C + bx + tx];
    __syncthreads();
#pragma unroll
    for (int i = 0; i < 32; i += 8)
        dst[(size_t)(bx + ty + i) * R + by + tx] = tile[tx][ty + i];
}

// ------------------- MLP GEMM: Y = act(X @ WT^T + bias) --------------------
// CTA tile 128x256, warp 64x64, k64 chunks, bulk-copy double buffer,
// one __syncthreads per chunk.
#define LDK64   68
#define A64_SZ  (128 * LDK64 * 4)    // 34816
#define B64_SZ  (256 * LDK64 * 4)    // 69632
#define MLP_MB_OFF (2 * (A64_SZ + B64_SZ))        // 208896
#define MLP_SMEM   (MLP_MB_OFF + 16)

__global__ void __launch_bounds__(256)
mlp_tc(const float* __restrict__ X, const float* __restrict__ WT,
       const float* __restrict__ bias, float* __restrict__ Y,
       int K, int N, int relu) {
    extern __shared__ char sm[];
    const uint32_t sbase = smem_u32(sm);
    const uint32_t Aoff[2] = {0u, A64_SZ};
    const uint32_t Boff[2] = {2 * A64_SZ, 2 * A64_SZ + B64_SZ};
    const uint32_t mb = sbase + MLP_MB_OFF;       // mb+0, mb+8

    const int t = threadIdx.x, w = t >> 5, q = (t & 31) >> 2, c = t & 3;
    const int wr = w & 1, wc = w >> 1;
    const int row0 = blockIdx.y * 128, col0 = blockIdx.x * 256;

    if (t == 0) { MBAR_INIT(mb, 256); MBAR_INIT(mb + 8, 256); }
    __syncthreads();

    float acc[4][8][4];
#pragma unroll
    for (int mi = 0; mi < 4; mi++)
#pragma unroll
        for (int ni = 0; ni < 8; ni++)
#pragma unroll
            for (int e = 0; e < 4; e++) acc[mi][ni][e] = 0.f;

    // per-thread row bulk copies: t<128 -> A row t + B row t (512 B);
    // t>=128 -> B row t (256 B).
    auto issue_chunk = [&](int j, int buf) {
        uint32_t m = mb + buf * 8;
        if (t < 128) {
            mbar_arrive_tx(m, 512);
            bulk_cp(sbase + Aoff[buf] + (uint32_t)t * (LDK64 * 4),
                    X + (size_t)(row0 + t) * K + j * 64, 256, m);
        } else {
            mbar_arrive_tx(m, 256);
        }
        bulk_cp(sbase + Boff[buf] + (uint32_t)t * (LDK64 * 4),
                WT + (size_t)(col0 + t) * K + j * 64, 256, m);
    };

    const int nch = K / 64;
    issue_chunk(0, 0);
    for (int j = 0; j < nch; j++) {
        MBAR_WAIT(mb + (j & 1) * 8, (j >> 1) & 1);
        __syncthreads();                           // all warps done compute(j-1)
        if (j + 1 < nch) issue_chunk(j + 1, (j + 1) & 1);
        const float* ab = (const float*)(sm + Aoff[j & 1]);
        const float* bb = (const float*)(sm + Boff[j & 1]);
        const float* aw = ab + (wr * 64 + q) * LDK64 + c;
        const float* bw = bb + (wc * 64 + q) * LDK64 + c;
        compute_k32<LDK64, LDK64>(aw, bw, acc);
        compute_k32<LDK64, LDK64>(aw + 32, bw + 32, acc);
    }

#pragma unroll
    for (int mi = 0; mi < 4; mi++) {
        int rg = row0 + wr * 64 + mi * 16 + q;
#pragma unroll
        for (int ni = 0; ni < 8; ni++) {
            int cg = col0 + wc * 64 + ni * 8 + 2 * c;
            float2 bv = *(const float2*)(bias + cg);
            float v0 = acc[mi][ni][0] + bv.x;
            float v1 = acc[mi][ni][1] + bv.y;
            float v2 = acc[mi][ni][2] + bv.x;
            float v3 = acc[mi][ni][3] + bv.y;
            if (relu) {
                v0 = fmaxf(v0, 0.f); v1 = fmaxf(v1, 0.f);
                v2 = fmaxf(v2, 0.f); v3 = fmaxf(v3, 0.f);
            }
            *(float2*)&Y[(size_t)rg * N + cg] = make_float2(v0, v1);
            *(float2*)&Y[(size_t)(rg + 8) * N + cg] = make_float2(v2, v3);
        }
    }
}

// ---------------- fused distance + partial min ------------------------------
// CTA = (bank quarter, 128-row tile); P tile stationary; bank streamed in
// 256-entry n-tiles x 8 k32 chunks via per-row bulk copies.
#define LDK32   36
#define BCH_SZ  (256 * LDK32 * 4)                // 36864
#define AS_LD   260
#define AS_SZ   (128 * AS_LD * 4)                // 133120
#define RED_OFF (AS_SZ + 2 * BCH_SZ)             // 206848
#define DMB_OFF (RED_OFF + 4 * 128 * 4)          // 208896
#define DIST_SMEM (DMB_OFF + 16)

__global__ void __launch_bounds__(256)
dist_tc(const float* __restrict__ P, const float* __restrict__ MBp) {
    extern __shared__ char sm[];
    const uint32_t sbase = smem_u32(sm);
    float* As = (float*)sm;
    const uint32_t Boff[2] = {AS_SZ, AS_SZ + BCH_SZ};
    float* red = (float*)(sm + RED_OFF);
    const uint32_t mb = sbase + DMB_OFF;

    const int t = threadIdx.x, w = t >> 5, q = (t & 31) >> 2, c = t & 3;
    const int wr = w & 1, wc = w >> 1;
    const int row0 = blockIdx.y * 128;
    const int qbase = blockIdx.x * (M_BANK / 4);

    if (t == 0) { MBAR_INIT(mb, 256); MBAR_INIT(mb + 8, 256); }

    // stationary P tile [128][260]
#pragma unroll
    for (int i = 0; i < 32; i++) {
        int f = t + i * 256;
        int rr = f >> 6, cq = (f & 63) * 4;
        *(float4*)(As + rr * AS_LD + cq) =
            *(const float4*)(P + (size_t)(row0 + rr) * C_D + cq);
    }
    __syncthreads();                              // mbar init + As visible

    // per-thread: one 128 B bank-row piece per chunk
    auto issue_chunk = [&](int jj, int buf) {
        int nt = jj >> 3, kc = jj & 7;
        uint32_t m = mb + buf * 8;
        mbar_arrive_tx(m, 128);
        bulk_cp(sbase + Boff[buf] + (uint32_t)t * (LDK32 * 4),
                MBp + (size_t)(qbase + nt * 256 + t) * C_D + kc * 32, 128, m);
    };

    float acc[4][8][4];
#pragma unroll
    for (int mi = 0; mi < 4; mi++)
#pragma unroll
        for (int ni = 0; ni < 8; ni++)
#pragma unroll
            for (int e = 0; e < 4; e++) acc[mi][ni][e] = 0.f;
    float runmin[4][2];
#pragma unroll
    for (int mi = 0; mi < 4; mi++) { runmin[mi][0] = 3.402823e38f; runmin[mi][1] = 3.402823e38f; }

    const float* aw0 = As + (wr * 64 + q) * AS_LD + c;

    issue_chunk(0, 0);
    const int NCH = (M_BANK / 4 / 256) * 8;      // 128 chunks
    for (int jj = 0; jj < NCH; jj++) {
        MBAR_WAIT(mb + (jj & 1) * 8, (jj >> 1) & 1);
        __syncthreads();                          // all warps done compute(jj-1)
        if (jj + 1 < NCH) issue_chunk(jj + 1, (jj + 1) & 1);
        const int kc = jj & 7;
        const float* bb = (const float*)(sm + Boff[jj & 1]);
        compute_k32<AS_LD, LDK32>(aw0 + kc * 32, bb + (wc * 64 + q) * LDK32 + c, acc);
        if (kc == 7) {
            const int nt = jj >> 3;
            const float* m2p = g_m2 + qbase + nt * 256 + wc * 64 + 2 * c;
#pragma unroll
            for (int mi = 0; mi < 4; mi++) {
                float m0 = runmin[mi][0], m1 = runmin[mi][1];
#pragma unroll
                for (int ni = 0; ni < 8; ni++) {
                    float2 m2v = *(const float2*)(m2p + ni * 8);
                    m0 = fminf(m0, fmaf(-2.f, acc[mi][ni][0], m2v.x));
                    m0 = fminf(m0, fmaf(-2.f, acc[mi][ni][1], m2v.y));
                    m1 = fminf(m1, fmaf(-2.f, acc[mi][ni][2], m2v.x));
                    m1 = fminf(m1, fmaf(-2.f, acc[mi][ni][3], m2v.y));
                    acc[mi][ni][0] = 0.f; acc[mi][ni][1] = 0.f;
                    acc[mi][ni][2] = 0.f; acc[mi][ni][3] = 0.f;
                }
                runmin[mi][0] = m0; runmin[mi][1] = m1;
            }
        }
    }

    // lane reduction (4 lanes share each row), then cross-warp via smem
#pragma unroll
    for (int mi = 0; mi < 4; mi++)
#pragma unroll
        for (int s = 0; s < 2; s++) {
            float v = runmin[mi][s];
            v = fminf(v, __shfl_xor_sync(0xffffffffu, v, 1));
            v = fminf(v, __shfl_xor_sync(0xffffffffu, v, 2));
            if (c == 0) red[wc * 128 + wr * 64 + mi * 16 + s * 8 + q] = v;
        }
    __syncthreads();
    if (t < 128) {
        float m = fminf(fminf(red[t], red[128 + t]), fminf(red[256 + t], red[384 + t]));
        g_pmin[(size_t)blockIdx.x * R_TOTAL + row0 + t] = m;
    }
}

// ------------------------------ combine ------------------------------------
__global__ void combine_kernel(float* __restrict__ out) {
    int r = blockIdx.x * blockDim.x + threadIdx.x;
    float m = fminf(fminf(g_pmin[r], g_pmin[R_TOTAL + r]),
                    fminf(g_pmin[2 * R_TOTAL + r], g_pmin[3 * R_TOTAL + r]));
    out[r] = sqrtf(fmaxf(g_x2[r] + m, 0.f));
}

// ---------------------------------------------------------------------------
extern "C" void kernel_launch(void* const* d_in, const int* in_sizes, int n_in,
                              void* d_out, int out_size) {
    (void)in_sizes; (void)n_in; (void)out_size;
    const float* features = (const float*)d_in[0];
    const float* W1       = (const float*)d_in[1];
    const float* b1       = (const float*)d_in[2];
    const float* W2       = (const float*)d_in[3];
    const float* b2       = (const float*)d_in[4];
    const float* MBp      = (const float*)d_in[5];
    float* out            = (float*)d_out;

    float *H, *Pp, *W1T, *W2T, *m2p, *x2p;
    cudaGetSymbolAddress((void**)&H, g_H);
    cudaGetSymbolAddress((void**)&Pp, g_P);
    cudaGetSymbolAddress((void**)&W1T, g_W1T);
    cudaGetSymbolAddress((void**)&W2T, g_W2T);
    cudaGetSymbolAddress((void**)&m2p, g_m2);
    cudaGetSymbolAddress((void**)&x2p, g_x2);

    cudaFuncSetAttribute(mlp_tc, cudaFuncAttributeMaxDynamicSharedMemorySize, MLP_SMEM);
    cudaFuncSetAttribute(dist_tc, cudaFuncAttributeMaxDynamicSharedMemorySize, DIST_SMEM);

    transpose32<<<dim3(C_HID / 32, C_IN / 32), 256>>>(W1, W1T, C_IN, C_HID);
    transpose32<<<dim3(C_D / 32, C_HID / 32), 256>>>(W2, W2T, C_HID, C_D);
    rowsq_kernel<<<M_BANK / 256, 256>>>(MBp, m2p);
    mlp_tc<<<dim3(C_HID / 256, R_TOTAL / 128), 256, MLP_SMEM>>>(features, W1T, b1, H,
                                                                C_IN, C_HID, 1);
    mlp_tc<<<dim3(C_D / 256, R_TOTAL / 128), 256, MLP_SMEM>>>(H, W2T, b2, Pp,
                                                              C_HID, C_D, 0);
    rowsq_kernel<<<R_TOTAL / 256, 256>>>(Pp, x2p);
    dist_tc<<<dim3(4, R_TOTAL / 128), 256, DIST_SMEM>>>(Pp, MBp);
    combine_kernel<<<R_TOTAL / 256, 256>>>(out);
}

// round 7
// speedup vs baseline: 1.7101x; 1.7101x over previous
#include <cuda_runtime.h>
#include <cuda_fp16.h>
#include <cstdint>

// ---------------------------------------------------------------------------
// PatchCoreAnomalyHead: MLP in tf32 mma.sync, distance GEMM in fp16
// m16n8k16 mma.sync (x^2/m^2 exact fp32; only cross term fp16).
// ---------------------------------------------------------------------------

#define R_TOTAL 32768
#define C_IN    1024
#define C_HID   512
#define C_D     256
#define M_BANK  16384

__device__ float  g_H[(size_t)R_TOTAL * C_HID];
__device__ float  g_P[(size_t)R_TOTAL * C_D];
__device__ __half g_P16[(size_t)R_TOTAL * C_D];
__device__ __half g_MB16[(size_t)M_BANK * C_D];
__device__ float  g_W1T[(size_t)C_HID * C_IN];
__device__ float  g_W2T[(size_t)C_D * C_HID];
__device__ float  g_m2[M_BANK];
__device__ float  g_x2[R_TOTAL];
__device__ float  g_pmin[4 * R_TOTAL];

// ---------------------------- helpers --------------------------------------
__device__ __forceinline__ uint32_t smem_u32(const void* p) {
    uint32_t a;
    asm("{ .reg .u64 t; cvta.to.shared.u64 t, %1; cvt.u32.u64 %0, t; }"
        : "=r"(a) : "l"(p));
    return a;
}
__device__ __forceinline__ void cp16(uint32_t dst, const void* src) {
    asm volatile("cp.async.cg.shared.global [%0], [%1], 16;" :: "r"(dst), "l"(src));
}
#define CP_COMMIT() asm volatile("cp.async.commit_group;" ::: "memory")
#define CP_WAIT0()  asm volatile("cp.async.wait_group 0;" ::: "memory")

__device__ __forceinline__ void mma_tf32(float (&d)[4],
                                         const uint32_t (&a)[4],
                                         const uint32_t (&b)[2]) {
    asm volatile(
        "mma.sync.aligned.m16n8k8.row.col.f32.tf32.tf32.f32 "
        "{%0,%1,%2,%3}, {%4,%5,%6,%7}, {%8,%9}, {%0,%1,%2,%3};"
        : "+f"(d[0]), "+f"(d[1]), "+f"(d[2]), "+f"(d[3])
        : "r"(a[0]), "r"(a[1]), "r"(a[2]), "r"(a[3]), "r"(b[0]), "r"(b[1]));
}
__device__ __forceinline__ void mma_f16(float (&d)[4],
                                        const uint32_t (&a)[4],
                                        const uint32_t (&b)[2]) {
    asm volatile(
        "mma.sync.aligned.m16n8k16.row.col.f32.f16.f16.f32 "
        "{%0,%1,%2,%3}, {%4,%5,%6,%7}, {%8,%9}, {%0,%1,%2,%3};"
        : "+f"(d[0]), "+f"(d[1]), "+f"(d[2]), "+f"(d[3])
        : "r"(a[0]), "r"(a[1]), "r"(a[2]), "r"(a[3]), "r"(b[0]), "r"(b[1]));
}

// tf32 k=32 slab, warp tile 64x64. ALD,BLD ≡ 4 (mod 32): conflict-free.
template <int ALD, int BLD>
__device__ __forceinline__ void compute_k32(const float* __restrict__ aw,
                                            const float* __restrict__ bw,
                                            float (&acc)[4][8][4]) {
#pragma unroll
    for (int s = 0; s < 4; s++) {
        const int k0 = s * 8;
        uint32_t a[4][4], b[8][2];
#pragma unroll
        for (int mi = 0; mi < 4; mi++) {
            const uint32_t* p = (const uint32_t*)(aw + mi * 16 * ALD + k0);
            a[mi][0] = p[0];
            a[mi][1] = p[8 * ALD];
            a[mi][2] = p[4];
            a[mi][3] = p[8 * ALD + 4];
        }
#pragma unroll
        for (int ni = 0; ni < 8; ni++) {
            const uint32_t* p = (const uint32_t*)(bw + ni * 8 * BLD + k0);
            b[ni][0] = p[0];
            b[ni][1] = p[4];
        }
#pragma unroll
        for (int mi = 0; mi < 4; mi++)
#pragma unroll
            for (int ni = 0; ni < 8; ni++)
                mma_tf32(acc[mi][ni], a[mi], b[ni]);
    }
}

// fp16 k=64 slab, warp tile 64x64 (4 k16 steps x 32 MMAs).
// Strides in HALF units; ALD2,BLD2 with (LD2/2) ≡ 4 (mod 32): conflict-free.
template <int ALD2, int BLD2>
__device__ __forceinline__ void compute_k64h(const __half* __restrict__ aw,
                                             const __half* __restrict__ bw,
                                             float (&acc)[4][8][4]) {
#pragma unroll
    for (int s = 0; s < 4; s++) {
        const int k0 = s * 16;
        uint32_t a[4][4], b[8][2];
#pragma unroll
        for (int mi = 0; mi < 4; mi++) {
            const __half* p = aw + mi * 16 * ALD2 + k0;
            a[mi][0] = *(const uint32_t*)(p);
            a[mi][1] = *(const uint32_t*)(p + 8 * ALD2);
            a[mi][2] = *(const uint32_t*)(p + 8);
            a[mi][3] = *(const uint32_t*)(p + 8 * ALD2 + 8);
        }
#pragma unroll
        for (int ni = 0; ni < 8; ni++) {
            const __half* p = bw + ni * 8 * BLD2 + k0;
            b[ni][0] = *(const uint32_t*)(p);
            b[ni][1] = *(const uint32_t*)(p + 8);
        }
#pragma unroll
        for (int mi = 0; mi < 4; mi++)
#pragma unroll
            for (int ni = 0; ni < 8; ni++)
                mma_f16(acc[mi][ni], a[mi], b[ni]);
    }
}

// ------------------------- small prep kernels ------------------------------
__global__ void rowsq_kernel(const float* __restrict__ src, float* __restrict__ dst) {
    int i = blockIdx.x * blockDim.x + threadIdx.x;
    const float4* p = (const float4*)(src + (size_t)i * C_D);
    float s = 0.f;
#pragma unroll 8
    for (int q = 0; q < C_D / 4; q++) {
        float4 v = p[q];
        s += v.x * v.x + v.y * v.y + v.z * v.z + v.w * v.w;
    }
    dst[i] = s;
}
__global__ void conv_half_kernel(const float* __restrict__ src, __half* __restrict__ dst) {
    int i = blockIdx.x * blockDim.x + threadIdx.x;       // float4 index
    float4 v = ((const float4*)src)[i];
    __half2* d = (__half2*)(dst + (size_t)i * 4);
    d[0] = __floats2half2_rn(v.x, v.y);
    d[1] = __floats2half2_rn(v.z, v.w);
}
__global__ void transpose32(const float* __restrict__ src, float* __restrict__ dst,
                            int R, int C) {
    __shared__ float tile[32][33];
    int bx = blockIdx.x * 32, by = blockIdx.y * 32;
    int tx = threadIdx.x & 31, ty = threadIdx.x >> 5;
#pragma unroll
    for (int i = 0; i < 32; i += 8)
        tile[ty + i][tx] = src[(size_t)(by + ty + i) * C + bx + tx];
    __syncthreads();
#pragma unroll
    for (int i = 0; i < 32; i += 8)
        dst[(size_t)(bx + ty + i) * R + by + tx] = tile[tx][ty + i];
}

// ------------------- MLP GEMM (tf32): Y = act(X @ WT^T + b) ----------------
// CTA 128x256, warp 64x64, k64 chunks, cp.async double buffer (R5 version).
#define LDK64   68
#define A64_SZ  (128 * LDK64 * 4)
#define B64_SZ  (256 * LDK64 * 4)
#define MLP_SMEM (2 * (A64_SZ + B64_SZ))   // 208896

__global__ void __launch_bounds__(256)
mlp_tc(const float* __restrict__ X, const float* __restrict__ WT,
       const float* __restrict__ bias, float* __restrict__ Y,
       __half* __restrict__ Y16, int K, int N, int relu) {
    extern __shared__ char sm[];
    const uint32_t sbase = smem_u32(sm);
    const uint32_t Aoff[2] = {0u, A64_SZ};
    const uint32_t Boff[2] = {2 * A64_SZ, 2 * A64_SZ + B64_SZ};

    const int t = threadIdx.x, w = t >> 5, q = (t & 31) >> 2, c = t & 3;
    const int wr = w & 1, wc = w >> 1;
    const int row0 = blockIdx.y * 128, col0 = blockIdx.x * 256;
    const int cr = t >> 4, c16 = (t & 15) * 4;

    float acc[4][8][4];
#pragma unroll
    for (int mi = 0; mi < 4; mi++)
#pragma unroll
        for (int ni = 0; ni < 8; ni++)
#pragma unroll
            for (int e = 0; e < 4; e++) acc[mi][ni][e] = 0.f;

    auto copy_chunk = [&](int j, int buf) {
#pragma unroll
        for (int i = 0; i < 8; i++) {
            int rr = cr + i * 16;
            cp16(sbase + Aoff[buf] + (uint32_t)(rr * LDK64 + c16) * 4,
                 X + (size_t)(row0 + rr) * K + j * 64 + c16);
        }
#pragma unroll
        for (int i = 0; i < 16; i++) {
            int rr = cr + i * 16;
            cp16(sbase + Boff[buf] + (uint32_t)(rr * LDK64 + c16) * 4,
                 WT + (size_t)(col0 + rr) * K + j * 64 + c16);
        }
    };

    const int nch = K / 64;
    copy_chunk(0, 0);
    CP_COMMIT();
    for (int j = 0; j < nch; j++) {
        CP_WAIT0();
        __syncthreads();
        if (j + 1 < nch) { copy_chunk(j + 1, (j + 1) & 1); CP_COMMIT(); }
        const float* ab = (const float*)(sm + Aoff[j & 1]);
        const float* bb = (const float*)(sm + Boff[j & 1]);
        const float* aw = ab + (wr * 64 + q) * LDK64 + c;
        const float* bw = bb + (wc * 64 + q) * LDK64 + c;
        compute_k32<LDK64, LDK64>(aw, bw, acc);
        compute_k32<LDK64, LDK64>(aw + 32, bw + 32, acc);
    }

#pragma unroll
    for (int mi = 0; mi < 4; mi++) {
        int rg = row0 + wr * 64 + mi * 16 + q;
#pragma unroll
        for (int ni = 0; ni < 8; ni++) {
            int cg = col0 + wc * 64 + ni * 8 + 2 * c;
            float2 bv = *(const float2*)(bias + cg);
            float v0 = acc[mi][ni][0] + bv.x;
            float v1 = acc[mi][ni][1] + bv.y;
            float v2 = acc[mi][ni][2] + bv.x;
            float v3 = acc[mi][ni][3] + bv.y;
            if (relu) {
                v0 = fmaxf(v0, 0.f); v1 = fmaxf(v1, 0.f);
                v2 = fmaxf(v2, 0.f); v3 = fmaxf(v3, 0.f);
            }
            *(float2*)&Y[(size_t)rg * N + cg] = make_float2(v0, v1);
            *(float2*)&Y[(size_t)(rg + 8) * N + cg] = make_float2(v2, v3);
            if (Y16) {
                *(__half2*)&Y16[(size_t)rg * N + cg] = __floats2half2_rn(v0, v1);
                *(__half2*)&Y16[(size_t)(rg + 8) * N + cg] = __floats2half2_rn(v2, v3);
            }
        }
    }
}

// ---------------- fused distance + partial min (fp16 MMA) ------------------
// CTA = (bank quarter, 128 P-rows); P16 tile stationary; bank16 streamed in
// 256-row n-tiles x k64 chunks, cp.async double buffer, one sync per chunk.
#define ALD2    264                                // halfs; 264/2=132 ≡ 4 mod 32
#define BLD2    72                                 // halfs; 72/2=36 ≡ 4 mod 32
#define AH_SZ   (128 * ALD2 * 2)                   // 67584
#define BH_SZ   (256 * BLD2 * 2)                   // 36864
#define RED_OFF (AH_SZ + 2 * BH_SZ)                // 141312
#define DIST_SMEM (RED_OFF + 4 * 128 * 4)          // 143360

__global__ void __launch_bounds__(256)
dist_tc(const __half* __restrict__ P16, const __half* __restrict__ MB16) {
    extern __shared__ char sm[];
    const uint32_t sbase = smem_u32(sm);
    const __half* As = (const __half*)sm;
    const uint32_t Boff[2] = {AH_SZ, AH_SZ + BH_SZ};
    float* red = (float*)(sm + RED_OFF);

    const int t = threadIdx.x, w = t >> 5, q = (t & 31) >> 2, c = t & 3;
    const int wr = w & 1, wc = w >> 1;
    const int row0 = blockIdx.y * 128;
    const int qbase = blockIdx.x * (M_BANK / 4);

    // stationary P16 tile: 128 rows x 256 halfs (512 B/row, 32 cp16 per row)
    {
        // 4096 cp16 total -> 16 per thread
#pragma unroll
        for (int i = 0; i < 16; i++) {
            int f = t + i * 256;
            int rr = f >> 5, seg = f & 31;        // seg = 16B unit
            cp16(sbase + (uint32_t)(rr * ALD2 + seg * 8) * 2,
                 P16 + (size_t)(row0 + rr) * C_D + seg * 8);
        }
    }

    auto copy_chunk = [&](int jj, int buf) {
        int nt = jj >> 2, kc = jj & 3;
        const __half* src = MB16 + (size_t)(qbase + nt * 256 + t) * C_D + kc * 64;
        uint32_t dst = sbase + Boff[buf] + (uint32_t)(t * BLD2) * 2;
#pragma unroll
        for (int i = 0; i < 8; i++)               // 64 halfs = 8 x 16B
            cp16(dst + i * 16, (const char*)src + i * 16);
    };

    float acc[4][8][4];
#pragma unroll
    for (int mi = 0; mi < 4; mi++)
#pragma unroll
        for (int ni = 0; ni < 8; ni++)
#pragma unroll
            for (int e = 0; e < 4; e++) acc[mi][ni][e] = 0.f;
    float runmin[4][2];
#pragma unroll
    for (int mi = 0; mi < 4; mi++) { runmin[mi][0] = 3.402823e38f; runmin[mi][1] = 3.402823e38f; }

    const __half* aw0 = As + (wr * 64 + q) * ALD2 + 2 * c;

    copy_chunk(0, 0);
    CP_COMMIT();
    const int NCH = (M_BANK / 4 / 256) * 4;       // 64 chunks (k64 each)
    for (int jj = 0; jj < NCH; jj++) {
        CP_WAIT0();
        __syncthreads();                          // covers As (jj=0) + reuse hazard
        if (jj + 1 < NCH) { copy_chunk(jj + 1, (jj + 1) & 1); CP_COMMIT(); }
        const int kc = jj & 3;
        const __half* bb = (const __half*)(sm + Boff[jj & 1]);
        compute_k64h<ALD2, BLD2>(aw0 + kc * 64, bb + (wc * 64 + q) * BLD2 + 2 * c, acc);
        if (kc == 3) {
            const int nt = jj >> 2;
            const float* m2p = g_m2 + qbase + nt * 256 + wc * 64 + 2 * c;
#pragma unroll
            for (int mi = 0; mi < 4; mi++) {
                float m0 = runmin[mi][0], m1 = runmin[mi][1];
#pragma unroll
                for (int ni = 0; ni < 8; ni++) {
                    float2 m2v = *(const float2*)(m2p + ni * 8);
                    m0 = fminf(m0, fmaf(-2.f, acc[mi][ni][0], m2v.x));
                    m0 = fminf(m0, fmaf(-2.f, acc[mi][ni][1], m2v.y));
                    m1 = fminf(m1, fmaf(-2.f, acc[mi][ni][2], m2v.x));
                    m1 = fminf(m1, fmaf(-2.f, acc[mi][ni][3], m2v.y));
                    acc[mi][ni][0] = 0.f; acc[mi][ni][1] = 0.f;
                    acc[mi][ni][2] = 0.f; acc[mi][ni][3] = 0.f;
                }
                runmin[mi][0] = m0; runmin[mi][1] = m1;
            }
        }
    }

    // lane reduction (4 lanes share each row), then cross-warp via smem
#pragma unroll
    for (int mi = 0; mi < 4; mi++)
#pragma unroll
        for (int s = 0; s < 2; s++) {
            float v = runmin[mi][s];
            v = fminf(v, __shfl_xor_sync(0xffffffffu, v, 1));
            v = fminf(v, __shfl_xor_sync(0xffffffffu, v, 2));
            if (c == 0) red[wc * 128 + wr * 64 + mi * 16 + s * 8 + q] = v;
        }
    __syncthreads();
    if (t < 128) {
        float m = fminf(fminf(red[t], red[128 + t]), fminf(red[256 + t], red[384 + t]));
        g_pmin[(size_t)blockIdx.x * R_TOTAL + row0 + t] = m;
    }
}

// ------------------------------ combine ------------------------------------
__global__ void combine_kernel(float* __restrict__ out) {
    int r = blockIdx.x * blockDim.x + threadIdx.x;
    float m = fminf(fminf(g_pmin[r], g_pmin[R_TOTAL + r]),
                    fminf(g_pmin[2 * R_TOTAL + r], g_pmin[3 * R_TOTAL + r]));
    out[r] = sqrtf(fmaxf(g_x2[r] + m, 0.f));
}

// ---------------------------------------------------------------------------
extern "C" void kernel_launch(void* const* d_in, const int* in_sizes, int n_in,
                              void* d_out, int out_size) {
    (void)in_sizes; (void)n_in; (void)out_size;
    const float* features = (const float*)d_in[0];
    const float* W1       = (const float*)d_in[1];
    const float* b1       = (const float*)d_in[2];
    const float* W2       = (const float*)d_in[3];
    const float* b2       = (const float*)d_in[4];
    const float* MBp      = (const float*)d_in[5];
    float* out            = (float*)d_out;

    float *H, *Pp, *W1T, *W2T, *m2p, *x2p;
    __half *P16, *MB16;
    cudaGetSymbolAddress((void**)&H, g_H);
    cudaGetSymbolAddress((void**)&Pp, g_P);
    cudaGetSymbolAddress((void**)&P16, g_P16);
    cudaGetSymbolAddress((void**)&MB16, g_MB16);
    cudaGetSymbolAddress((void**)&W1T, g_W1T);
    cudaGetSymbolAddress((void**)&W2T, g_W2T);
    cudaGetSymbolAddress((void**)&m2p, g_m2);
    cudaGetSymbolAddress((void**)&x2p, g_x2);

    cudaFuncSetAttribute(mlp_tc, cudaFuncAttributeMaxDynamicSharedMemorySize, MLP_SMEM);
    cudaFuncSetAttribute(dist_tc, cudaFuncAttributeMaxDynamicSharedMemorySize, DIST_SMEM);

    transpose32<<<dim3(C_HID / 32, C_IN / 32), 256>>>(W1, W1T, C_IN, C_HID);
    transpose32<<<dim3(C_D / 32, C_HID / 32), 256>>>(W2, W2T, C_HID, C_D);
    rowsq_kernel<<<M_BANK / 256, 256>>>(MBp, m2p);
    conv_half_kernel<<<(M_BANK * C_D / 4) / 256, 256>>>(MBp, MB16);
    mlp_tc<<<dim3(C_HID / 256, R_TOTAL / 128), 256, MLP_SMEM>>>(
        features, W1T, b1, H, (__half*)nullptr, C_IN, C_HID, 1);
    mlp_tc<<<dim3(C_D / 256, R_TOTAL / 128), 256, MLP_SMEM>>>(
        H, W2T, b2, Pp, P16, C_HID, C_D, 0);
    rowsq_kernel<<<R_TOTAL / 256, 256>>>(Pp, x2p);
    dist_tc<<<dim3(4, R_TOTAL / 128), 256, DIST_SMEM>>>(P16, MB16);
    combine_kernel<<<R_TOTAL / 256, 256>>>(out);
}

// round 8
// speedup vs baseline: 2.2263x; 1.3019x over previous
#include <cuda_runtime.h>
#include <cuda_fp16.h>
#include <cstdint>

// ---------------------------------------------------------------------------
// PatchCoreAnomalyHead: MLP tf32 mma.sync; distance GEMM fp16 m16n8k16 with
// 512-thread CTAs (4 warps/SMSP) for latency hiding.
// ---------------------------------------------------------------------------

#define R_TOTAL 32768
#define C_IN    1024
#define C_HID   512
#define C_D     256
#define M_BANK  16384
#define NSPLIT  8

__device__ float  g_H[(size_t)R_TOTAL * C_HID];
__device__ float  g_P[(size_t)R_TOTAL * C_D];
__device__ __half g_P16[(size_t)R_TOTAL * C_D];
__device__ __half g_MB16[(size_t)M_BANK * C_D];
__device__ float  g_W1T[(size_t)C_HID * C_IN];
__device__ float  g_W2T[(size_t)C_D * C_HID];
__device__ float  g_m2[M_BANK];
__device__ float  g_x2[R_TOTAL];
__device__ float  g_pmin[NSPLIT * R_TOTAL];

// ---------------------------- helpers --------------------------------------
__device__ __forceinline__ uint32_t smem_u32(const void* p) {
    uint32_t a;
    asm("{ .reg .u64 t; cvta.to.shared.u64 t, %1; cvt.u32.u64 %0, t; }"
        : "=r"(a) : "l"(p));
    return a;
}
__device__ __forceinline__ void cp16(uint32_t dst, const void* src) {
    asm volatile("cp.async.cg.shared.global [%0], [%1], 16;" :: "r"(dst), "l"(src));
}
#define CP_COMMIT() asm volatile("cp.async.commit_group;" ::: "memory")
#define CP_WAIT0()  asm volatile("cp.async.wait_group 0;" ::: "memory")

__device__ __forceinline__ void mma_tf32(float (&d)[4],
                                         const uint32_t (&a)[4],
                                         const uint32_t (&b)[2]) {
    asm volatile(
        "mma.sync.aligned.m16n8k8.row.col.f32.tf32.tf32.f32 "
        "{%0,%1,%2,%3}, {%4,%5,%6,%7}, {%8,%9}, {%0,%1,%2,%3};"
        : "+f"(d[0]), "+f"(d[1]), "+f"(d[2]), "+f"(d[3])
        : "r"(a[0]), "r"(a[1]), "r"(a[2]), "r"(a[3]), "r"(b[0]), "r"(b[1]));
}
__device__ __forceinline__ void mma_f16(float (&d)[4],
                                        const uint32_t (&a)[4],
                                        const uint32_t (&b)[2]) {
    asm volatile(
        "mma.sync.aligned.m16n8k16.row.col.f32.f16.f16.f32 "
        "{%0,%1,%2,%3}, {%4,%5,%6,%7}, {%8,%9}, {%0,%1,%2,%3};"
        : "+f"(d[0]), "+f"(d[1]), "+f"(d[2]), "+f"(d[3])
        : "r"(a[0]), "r"(a[1]), "r"(a[2]), "r"(a[3]), "r"(b[0]), "r"(b[1]));
}

// tf32 k=32 slab, warp tile 64x64 (MLP). ALD,BLD ≡ 4 (mod 32): conflict-free.
template <int ALD, int BLD>
__device__ __forceinline__ void compute_k32(const float* __restrict__ aw,
                                            const float* __restrict__ bw,
                                            float (&acc)[4][8][4]) {
#pragma unroll
    for (int s = 0; s < 4; s++) {
        const int k0 = s * 8;
        uint32_t a[4][4], b[8][2];
#pragma unroll
        for (int mi = 0; mi < 4; mi++) {
            const uint32_t* p = (const uint32_t*)(aw + mi * 16 * ALD + k0);
            a[mi][0] = p[0];
            a[mi][1] = p[8 * ALD];
            a[mi][2] = p[4];
            a[mi][3] = p[8 * ALD + 4];
        }
#pragma unroll
        for (int ni = 0; ni < 8; ni++) {
            const uint32_t* p = (const uint32_t*)(bw + ni * 8 * BLD + k0);
            b[ni][0] = p[0];
            b[ni][1] = p[4];
        }
#pragma unroll
        for (int mi = 0; mi < 4; mi++)
#pragma unroll
            for (int ni = 0; ni < 8; ni++)
                mma_tf32(acc[mi][ni], a[mi], b[ni]);
    }
}

// fp16 k=64 slab, warp tile 64x32 (dist). (LD2/2) ≡ 4 (mod 32): conflict-free.
template <int ALD2, int BLD2>
__device__ __forceinline__ void compute_k64h32(const __half* __restrict__ aw,
                                               const __half* __restrict__ bw,
                                               float (&acc)[4][4][4]) {
#pragma unroll
    for (int s = 0; s < 4; s++) {
        const int k0 = s * 16;
        uint32_t a[4][4], b[4][2];
#pragma unroll
        for (int mi = 0; mi < 4; mi++) {
            const __half* p = aw + mi * 16 * ALD2 + k0;
            a[mi][0] = *(const uint32_t*)(p);
            a[mi][1] = *(const uint32_t*)(p + 8 * ALD2);
            a[mi][2] = *(const uint32_t*)(p + 8);
            a[mi][3] = *(const uint32_t*)(p + 8 * ALD2 + 8);
        }
#pragma unroll
        for (int ni = 0; ni < 4; ni++) {
            const __half* p = bw + ni * 8 * BLD2 + k0;
            b[ni][0] = *(const uint32_t*)(p);
            b[ni][1] = *(const uint32_t*)(p + 8);
        }
#pragma unroll
        for (int mi = 0; mi < 4; mi++)
#pragma unroll
            for (int ni = 0; ni < 4; ni++)
                mma_f16(acc[mi][ni], a[mi], b[ni]);
    }
}

// ------------------------- small prep kernels ------------------------------
__global__ void rowsq_kernel(const float* __restrict__ src, float* __restrict__ dst) {
    int i = blockIdx.x * blockDim.x + threadIdx.x;
    const float4* p = (const float4*)(src + (size_t)i * C_D);
    float s = 0.f;
#pragma unroll 8
    for (int q = 0; q < C_D / 4; q++) {
        float4 v = p[q];
        s += v.x * v.x + v.y * v.y + v.z * v.z + v.w * v.w;
    }
    dst[i] = s;
}
__global__ void conv_half_kernel(const float* __restrict__ src, __half* __restrict__ dst) {
    int i = blockIdx.x * blockDim.x + threadIdx.x;
    float4 v = ((const float4*)src)[i];
    __half2* d = (__half2*)(dst + (size_t)i * 4);
    d[0] = __floats2half2_rn(v.x, v.y);
    d[1] = __floats2half2_rn(v.z, v.w);
}
__global__ void transpose32(const float* __restrict__ src, float* __restrict__ dst,
                            int R, int C) {
    __shared__ float tile[32][33];
    int bx = blockIdx.x * 32, by = blockIdx.y * 32;
    int tx = threadIdx.x & 31, ty = threadIdx.x >> 5;
#pragma unroll
    for (int i = 0; i < 32; i += 8)
        tile[ty + i][tx] = src[(size_t)(by + ty + i) * C + bx + tx];
    __syncthreads();
#pragma unroll
    for (int i = 0; i < 32; i += 8)
        dst[(size_t)(bx + ty + i) * R + by + tx] = tile[tx][ty + i];
}

// ------------------- MLP GEMM (tf32): Y = act(X @ WT^T + b) ----------------
#define LDK64   68
#define A64_SZ  (128 * LDK64 * 4)
#define B64_SZ  (256 * LDK64 * 4)
#define MLP_SMEM (2 * (A64_SZ + B64_SZ))

__global__ void __launch_bounds__(256)
mlp_tc(const float* __restrict__ X, const float* __restrict__ WT,
       const float* __restrict__ bias, float* __restrict__ Y,
       __half* __restrict__ Y16, int K, int N, int relu) {
    extern __shared__ char sm[];
    const uint32_t sbase = smem_u32(sm);
    const uint32_t Aoff[2] = {0u, A64_SZ};
    const uint32_t Boff[2] = {2 * A64_SZ, 2 * A64_SZ + B64_SZ};

    const int t = threadIdx.x, w = t >> 5, q = (t & 31) >> 2, c = t & 3;
    const int wr = w & 1, wc = w >> 1;
    const int row0 = blockIdx.y * 128, col0 = blockIdx.x * 256;
    const int cr = t >> 4, c16 = (t & 15) * 4;

    float acc[4][8][4];
#pragma unroll
    for (int mi = 0; mi < 4; mi++)
#pragma unroll
        for (int ni = 0; ni < 8; ni++)
#pragma unroll
            for (int e = 0; e < 4; e++) acc[mi][ni][e] = 0.f;

    auto copy_chunk = [&](int j, int buf) {
#pragma unroll
        for (int i = 0; i < 8; i++) {
            int rr = cr + i * 16;
            cp16(sbase + Aoff[buf] + (uint32_t)(rr * LDK64 + c16) * 4,
                 X + (size_t)(row0 + rr) * K + j * 64 + c16);
        }
#pragma unroll
        for (int i = 0; i < 16; i++) {
            int rr = cr + i * 16;
            cp16(sbase + Boff[buf] + (uint32_t)(rr * LDK64 + c16) * 4,
                 WT + (size_t)(col0 + rr) * K + j * 64 + c16);
        }
    };

    const int nch = K / 64;
    copy_chunk(0, 0);
    CP_COMMIT();
    for (int j = 0; j < nch; j++) {
        CP_WAIT0();
        __syncthreads();
        if (j + 1 < nch) { copy_chunk(j + 1, (j + 1) & 1); CP_COMMIT(); }
        const float* ab = (const float*)(sm + Aoff[j & 1]);
        const float* bb = (const float*)(sm + Boff[j & 1]);
        const float* aw = ab + (wr * 64 + q) * LDK64 + c;
        const float* bw = bb + (wc * 64 + q) * LDK64 + c;
        compute_k32<LDK64, LDK64>(aw, bw, acc);
        compute_k32<LDK64, LDK64>(aw + 32, bw + 32, acc);
    }

#pragma unroll
    for (int mi = 0; mi < 4; mi++) {
        int rg = row0 + wr * 64 + mi * 16 + q;
#pragma unroll
        for (int ni = 0; ni < 8; ni++) {
            int cg = col0 + wc * 64 + ni * 8 + 2 * c;
            float2 bv = *(const float2*)(bias + cg);
            float v0 = acc[mi][ni][0] + bv.x;
            float v1 = acc[mi][ni][1] + bv.y;
            float v2 = acc[mi][ni][2] + bv.x;
            float v3 = acc[mi][ni][3] + bv.y;
            if (relu) {
                v0 = fmaxf(v0, 0.f); v1 = fmaxf(v1, 0.f);
                v2 = fmaxf(v2, 0.f); v3 = fmaxf(v3, 0.f);
            }
            *(float2*)&Y[(size_t)rg * N + cg] = make_float2(v0, v1);
            *(float2*)&Y[(size_t)(rg + 8) * N + cg] = make_float2(v2, v3);
            if (Y16) {
                *(__half2*)&Y16[(size_t)rg * N + cg] = __floats2half2_rn(v0, v1);
                *(__half2*)&Y16[(size_t)(rg + 8) * N + cg] = __floats2half2_rn(v2, v3);
            }
        }
    }
}

// ---------------- fused distance + partial min (fp16, 512 thr) -------------
// CTA = (bank eighth, 256 P-rows). 16 warps (4x4): warp tile 64x32.
// P16 stationary [256][264] halfs; bank streamed in 128-row n-tiles x k64
// chunks, cp.async double buffer, one sync per chunk.
#define ALD2    264                                // halfs; 264/2 ≡ 4 mod 32
#define BLD2    72                                 // halfs; 72/2  ≡ 4 mod 32
#define AH_SZ   (256 * ALD2 * 2)                   // 135168
#define BH_SZ   (128 * BLD2 * 2)                   // 18432
#define RED_OFF (AH_SZ + 2 * BH_SZ)                // 172032
#define DIST_SMEM (RED_OFF + 4 * 256 * 4)          // 176128

__global__ void __launch_bounds__(512)
dist_tc(const __half* __restrict__ P16, const __half* __restrict__ MB16) {
    extern __shared__ char sm[];
    const uint32_t sbase = smem_u32(sm);
    const __half* As = (const __half*)sm;
    const uint32_t Boff[2] = {AH_SZ, AH_SZ + BH_SZ};
    float* red = (float*)(sm + RED_OFF);

    const int t = threadIdx.x, w = t >> 5, q = (t & 31) >> 2, c = t & 3;
    const int wr = w & 3, wc = w >> 2;             // 4 row-bands x 4 col-bands
    const int row0 = blockIdx.y * 256;
    const int qbase = blockIdx.x * (M_BANK / NSPLIT);

    // stationary P16 tile: 256 rows x 256 halfs (512 B/row)
#pragma unroll
    for (int i = 0; i < 16; i++) {
        int f = t + i * 512;
        int rr = f >> 5, seg = f & 31;
        cp16(sbase + (uint32_t)(rr * ALD2 + seg * 8) * 2,
             P16 + (size_t)(row0 + rr) * C_D + seg * 8);
    }

    // per chunk: 128 bank rows x 64 halfs (128 B/row) -> 2 cp16 per thread
    auto copy_chunk = [&](int jj, int buf) {
        int nt = jj >> 2, kc = jj & 3;
        int rr = t >> 2, seg = t & 3;
        const __half* src = MB16 + (size_t)(qbase + nt * 128 + rr) * C_D
                            + kc * 64 + seg * 16;
        uint32_t dst = sbase + Boff[buf] + (uint32_t)(rr * BLD2 + seg * 16) * 2;
        cp16(dst, src);
        cp16(dst + 16, src + 8);
    };

    float acc[4][4][4];
#pragma unroll
    for (int mi = 0; mi < 4; mi++)
#pragma unroll
        for (int ni = 0; ni < 4; ni++)
#pragma unroll
            for (int e = 0; e < 4; e++) acc[mi][ni][e] = 0.f;
    float runmin[4][2];
#pragma unroll
    for (int mi = 0; mi < 4; mi++) { runmin[mi][0] = 3.402823e38f; runmin[mi][1] = 3.402823e38f; }

    const __half* aw0 = As + (wr * 64 + q) * ALD2 + 2 * c;

    copy_chunk(0, 0);
    CP_COMMIT();
    const int NCH = (M_BANK / NSPLIT / 128) * 4;   // 64 chunks
    for (int jj = 0; jj < NCH; jj++) {
        CP_WAIT0();
        __syncthreads();                            // covers As (jj=0) + reuse
        if (jj + 1 < NCH) { copy_chunk(jj + 1, (jj + 1) & 1); CP_COMMIT(); }
        const int kc = jj & 3;
        const __half* bb = (const __half*)(sm + Boff[jj & 1]);
        compute_k64h32<ALD2, BLD2>(aw0 + kc * 64,
                                   bb + (wc * 32 + q) * BLD2 + 2 * c, acc);
        if (kc == 3) {
            const int nt = jj >> 2;
            const float* m2p = g_m2 + qbase + nt * 128 + wc * 32 + 2 * c;
#pragma unroll
            for (int mi = 0; mi < 4; mi++) {
                float m0 = runmin[mi][0], m1 = runmin[mi][1];
#pragma unroll
                for (int ni = 0; ni < 4; ni++) {
                    float2 m2v = *(const float2*)(m2p + ni * 8);
                    m0 = fminf(m0, fmaf(-2.f, acc[mi][ni][0], m2v.x));
                    m0 = fminf(m0, fmaf(-2.f, acc[mi][ni][1], m2v.y));
                    m1 = fminf(m1, fmaf(-2.f, acc[mi][ni][2], m2v.x));
                    m1 = fminf(m1, fmaf(-2.f, acc[mi][ni][3], m2v.y));
                    acc[mi][ni][0] = 0.f; acc[mi][ni][1] = 0.f;
                    acc[mi][ni][2] = 0.f; acc[mi][ni][3] = 0.f;
                }
                runmin[mi][0] = m0; runmin[mi][1] = m1;
            }
        }
    }

    // lane reduction (4 lanes share each row), then across the 4 col-band warps
#pragma unroll
    for (int mi = 0; mi < 4; mi++)
#pragma unroll
        for (int s = 0; s < 2; s++) {
            float v = runmin[mi][s];
            v = fminf(v, __shfl_xor_sync(0xffffffffu, v, 1));
            v = fminf(v, __shfl_xor_sync(0xffffffffu, v, 2));
            if (c == 0) red[wc * 256 + wr * 64 + mi * 16 + s * 8 + q] = v;
        }
    __syncthreads();
    if (t < 256) {
        float m = fminf(fminf(red[t], red[256 + t]),
                        fminf(red[512 + t], red[768 + t]));
        g_pmin[(size_t)blockIdx.x * R_TOTAL + row0 + t] = m;
    }
}

// ------------------------------ combine ------------------------------------
__global__ void combine_kernel(float* __restrict__ out) {
    int r = blockIdx.x * blockDim.x + threadIdx.x;
    float m = 3.402823e38f;
#pragma unroll
    for (int s = 0; s < NSPLIT; s++)
        m = fminf(m, g_pmin[(size_t)s * R_TOTAL + r]);
    out[r] = sqrtf(fmaxf(g_x2[r] + m, 0.f));
}

// ---------------------------------------------------------------------------
extern "C" void kernel_launch(void* const* d_in, const int* in_sizes, int n_in,
                              void* d_out, int out_size) {
    (void)in_sizes; (void)n_in; (void)out_size;
    const float* features = (const float*)d_in[0];
    const float* W1       = (const float*)d_in[1];
    const float* b1       = (const float*)d_in[2];
    const float* W2       = (const float*)d_in[3];
    const float* b2       = (const float*)d_in[4];
    const float* MBp      = (const float*)d_in[5];
    float* out            = (float*)d_out;

    float *H, *Pp, *W1T, *W2T, *m2p, *x2p;
    __half *P16, *MB16;
    cudaGetSymbolAddress((void**)&H, g_H);
    cudaGetSymbolAddress((void**)&Pp, g_P);
    cudaGetSymbolAddress((void**)&P16, g_P16);
    cudaGetSymbolAddress((void**)&MB16, g_MB16);
    cudaGetSymbolAddress((void**)&W1T, g_W1T);
    cudaGetSymbolAddress((void**)&W2T, g_W2T);
    cudaGetSymbolAddress((void**)&m2p, g_m2);
    cudaGetSymbolAddress((void**)&x2p, g_x2);

    cudaFuncSetAttribute(mlp_tc, cudaFuncAttributeMaxDynamicSharedMemorySize, MLP_SMEM);
    cudaFuncSetAttribute(dist_tc, cudaFuncAttributeMaxDynamicSharedMemorySize, DIST_SMEM);

    transpose32<<<dim3(C_HID / 32, C_IN / 32), 256>>>(W1, W1T, C_IN, C_HID);
    transpose32<<<dim3(C_D / 32, C_HID / 32), 256>>>(W2, W2T, C_HID, C_D);
    rowsq_kernel<<<M_BANK / 256, 256>>>(MBp, m2p);
    conv_half_kernel<<<(M_BANK * C_D / 4) / 256, 256>>>(MBp, MB16);
    mlp_tc<<<dim3(C_HID / 256, R_TOTAL / 128), 256, MLP_SMEM>>>(
        features, W1T, b1, H, (__half*)nullptr, C_IN, C_HID, 1);
    mlp_tc<<<dim3(C_D / 256, R_TOTAL / 128), 256, MLP_SMEM>>>(
        H, W2T, b2, Pp, P16, C_HID, C_D, 0);
    rowsq_kernel<<<R_TOTAL / 256, 256>>>(Pp, x2p);
    dist_tc<<<dim3(NSPLIT, R_TOTAL / 256), 512, DIST_SMEM>>>(P16, MB16);
    combine_kernel<<<R_TOTAL / 256, 256>>>(out);
}